// round 9
// baseline (speedup 1.0000x reference)
#include <cuda_runtime.h>
#include <cstdint>

#define NT 512
#define NS 64

typedef unsigned long long u64;

// ---------------- packed weights, k2-interleaved by gate --------------------------------
// g_whRZ[k2*256+j] = (w_hh_r[j][2k2], w_hh_r[j][2k2+1], w_hh_z[j][2k2], w_hh_z[j][2k2+1])
// g_whN [k2*256+j] = (w_hh_n[j][2k2], w_hh_n[j][2k2+1])
__device__ float4 g_whRZ[128 * 256];
__device__ float2 g_whN[128 * 256];
__device__ float4 g_wiRZ[32 * 256];
__device__ float2 g_wiN[32 * 256];
__device__ float2 g_wbP[128 * 256];

// ---------------- f32x2 helpers ---------------------------------------------------------
__device__ __forceinline__ u64 pk2(float a, float b) {
    u64 r;
    asm("mov.b64 %0,{%1,%2};" : "=l"(r)
        : "r"(__float_as_uint(a)), "r"(__float_as_uint(b)));
    return r;
}
__device__ __forceinline__ float2 upk2(u64 v) {
    unsigned lo, hi;
    asm("mov.b64 {%0,%1},%2;" : "=r"(lo), "=r"(hi) : "l"(v));
    return make_float2(__uint_as_float(lo), __uint_as_float(hi));
}
__device__ __forceinline__ void ffma2(u64& d, u64 a, u64 b) {
    asm("fma.rn.f32x2 %0,%1,%2,%3;" : "=l"(d) : "l"(a), "l"(b), "l"(d));
}
__device__ __forceinline__ float hsum2(u64 v) {
    float2 f = upk2(v);
    return f.x + f.y;
}
__device__ __forceinline__ float sigmoidf_(float x) { return 1.f / (1.f + __expf(-x)); }
__device__ __forceinline__ float tanhf_(float x) { return 1.f - 2.f / (__expf(2.f * x) + 1.f); }

// ---------------- prep: transpose + pack ------------------------------------------------
__global__ void __launch_bounds__(256) prep_kernel(const float* __restrict__ w_ih,
                                                   const float* __restrict__ w_hh,
                                                   const float* __restrict__ w_base) {
    int idx = blockIdx.x * 256 + threadIdx.x;
    if (idx < 32768) {  // g_whRZ
        int k2 = idx >> 8, j = idx & 255;
        const float* wr = w_hh + (size_t)j * 256;
        const float* wz = w_hh + (size_t)(256 + j) * 256;
        g_whRZ[idx] = make_float4(wr[2 * k2], wr[2 * k2 + 1], wz[2 * k2], wz[2 * k2 + 1]);
        return;
    }
    idx -= 32768;
    if (idx < 32768) {  // g_whN
        int k2 = idx >> 8, j = idx & 255;
        const float* wn = w_hh + (size_t)(512 + j) * 256;
        g_whN[idx] = make_float2(wn[2 * k2], wn[2 * k2 + 1]);
        return;
    }
    idx -= 32768;
    if (idx < 8192) {  // g_wiRZ
        int k2 = idx >> 8, j = idx & 255;
        const float* wr = w_ih + (size_t)j * 64;
        const float* wz = w_ih + (size_t)(256 + j) * 64;
        g_wiRZ[idx] = make_float4(wr[2 * k2], wr[2 * k2 + 1], wz[2 * k2], wz[2 * k2 + 1]);
        return;
    }
    idx -= 8192;
    if (idx < 8192) {  // g_wiN
        int k2 = idx >> 8, j = idx & 255;
        const float* wn = w_ih + (size_t)(512 + j) * 64;
        g_wiN[idx] = make_float2(wn[2 * k2], wn[2 * k2 + 1]);
        return;
    }
    idx -= 8192;
    if (idx < 32768) {  // g_wbP
        int k2 = idx >> 8, j = idx & 255;
        const float* row = w_base + (size_t)j * 256;
        g_wbP[idx] = make_float2(row[2 * k2], row[2 * k2 + 1]);
    }
}

// ---------------- main: 128 CTAs x 512 threads; 8 rows/CTA; thread = (j, k-half) --------
// hs[k2][bp] floats: [h[2bp][2k2], h[2bp][2k2+1], h[2bp+1][2k2], h[2bp+1][2k2+1]]
__global__ void __launch_bounds__(512, 1) actor_kernel(
    const float* __restrict__ x, const float* __restrict__ b_ih,
    const float* __restrict__ b_hh, const float* __restrict__ b_base,
    const float* __restrict__ w_dir, const float* __restrict__ b_dir,
    const float* __restrict__ w_mag, const float* __restrict__ b_mag,
    float* __restrict__ out) {
    __shared__ ulonglong2 hs[128][4];     // 8 KB
    __shared__ ulonglong2 xs[2][32][4];   // 4 KB
    __shared__ float4 exch[8][256];       // 32 KB

    const int tid = threadIdx.x;
    const int j = tid & 255;   // gate dim
    const int kh = tid >> 8;   // k-half
    const int bbase = blockIdx.x * 8;

    ((ulonglong2*)hs)[tid] = make_ulonglong2(0ULL, 0ULL);

    const float br = b_ih[j] + b_hh[j];
    const float bz = b_ih[256 + j] + b_hh[256 + j];
    const float bi = b_ih[512 + j];
    const float bh = b_hh[512 + j];

    float hreg[8];
#pragma unroll
    for (int i = 0; i < 8; i++) hreg[i] = 0.f;

    // x prefetch: threads 0..127 each own (row, 4-float chunk)
    const int xrow = tid >> 4, xc = tid & 15;
    const float* xptr = x + (size_t)(bbase + xrow) * NT * NS + xc * 4;
    float4 xr = make_float4(0.f, 0.f, 0.f, 0.f);
    if (tid < 128) xr = *(const float4*)xptr;

    // single-base weight pointers; inner offsets are k2*const immediates
    const ulonglong2* __restrict__ pRZ = (const ulonglong2*)g_whRZ + (size_t)kh * 64 * 256 + j;
    const u64* __restrict__ pN = (const u64*)g_whN + (size_t)kh * 64 * 256 + j;
    const ulonglong2* __restrict__ piRZ = (const ulonglong2*)g_wiRZ + (size_t)kh * 16 * 256 + j;
    const u64* __restrict__ piN = (const u64*)g_wiN + (size_t)kh * 16 * 256 + j;
    const ulonglong2* hbase = &hs[kh * 64][0];

    for (int t = 0; t < NT; ++t) {
        const int buf = t & 1;
        if (tid < 128) {
            ((u64*)&xs[buf][2 * xc][xrow >> 1])[xrow & 1] = pk2(xr.x, xr.y);
            ((u64*)&xs[buf][2 * xc + 1][xrow >> 1])[xrow & 1] = pk2(xr.z, xr.w);
            if (t + 1 < NT) xr = *(const float4*)(xptr + (size_t)(t + 1) * NS);
        }
        __syncthreads();  // x_t staged; h(t-1) visible; exch free

        u64 aR[8], aZ[8], aNi[8], aNh[8];
#pragma unroll
        for (int b = 0; b < 8; b++) { aR[b] = aZ[b] = aNi[b] = aNh[b] = 0ULL; }

        // input part: 16 k-pairs for this k-half
        const ulonglong2* xbase = &xs[buf][kh * 16][0];
#pragma unroll 4
        for (int k2 = 0; k2 < 16; ++k2) {
            ulonglong2 wrz = piRZ[k2 * 256];   // LDG.128: (r-pair, z-pair)
            u64 wn = piN[k2 * 256];            // LDG.64 : n-pair
#pragma unroll
            for (int bp = 0; bp < 4; ++bp) {
                ulonglong2 hv = xbase[k2 * 4 + bp];
                ffma2(aR[2 * bp], wrz.x, hv.x);
                ffma2(aR[2 * bp + 1], wrz.x, hv.y);
                ffma2(aZ[2 * bp], wrz.y, hv.x);
                ffma2(aZ[2 * bp + 1], wrz.y, hv.y);
                ffma2(aNi[2 * bp], wn, hv.x);
                ffma2(aNi[2 * bp + 1], wn, hv.y);
            }
        }
        // recurrent part: 64 k-pairs for this k-half
#pragma unroll 4
        for (int k2 = 0; k2 < 64; ++k2) {
            ulonglong2 wrz = pRZ[k2 * 256];
            u64 wn = pN[k2 * 256];
#pragma unroll
            for (int bp = 0; bp < 4; ++bp) {
                ulonglong2 hv = hbase[k2 * 4 + bp];
                ffma2(aR[2 * bp], wrz.x, hv.x);
                ffma2(aR[2 * bp + 1], wrz.x, hv.y);
                ffma2(aZ[2 * bp], wrz.y, hv.x);
                ffma2(aZ[2 * bp + 1], wrz.y, hv.y);
                ffma2(aNh[2 * bp], wn, hv.x);
                ffma2(aNh[2 * bp + 1], wn, hv.y);
            }
        }

        // kh=1 publishes horizontally-reduced partials
        if (kh) {
#pragma unroll
            for (int b = 0; b < 8; ++b)
                exch[b][j] = make_float4(hsum2(aR[b]), hsum2(aZ[b]),
                                         hsum2(aNi[b]), hsum2(aNh[b]));
        }
        __syncthreads();  // exch ready; all hs reads done

        // kh=0 combines, does gate math, writes new h
        if (!kh) {
            const int k2w = j >> 1, par = j & 1;
#pragma unroll
            for (int b = 0; b < 8; ++b) {
                float4 p = exch[b][j];
                float r = sigmoidf_(hsum2(aR[b]) + p.x + br);
                float z = sigmoidf_(hsum2(aZ[b]) + p.y + bz);
                float n = tanhf_(hsum2(aNi[b]) + p.z + bi +
                                 r * (hsum2(aNh[b]) + p.w + bh));
                hreg[b] = (1.f - z) * n + z * hreg[b];
                ((float*)&hs[k2w][b >> 1])[(b & 1) * 2 + par] = hreg[b];
            }
        }
    }
    __syncthreads();  // final h visible

    // base layer (k-split): hb[b][j] = relu(h[b] . w_base[j] + b_base[j])
    {
        u64 aB[8];
#pragma unroll
        for (int b = 0; b < 8; b++) aB[b] = 0ULL;
        const u64* __restrict__ pWb = (const u64*)g_wbP + (size_t)kh * 64 * 256 + j;
#pragma unroll 4
        for (int k2 = 0; k2 < 64; ++k2) {
            u64 wb = pWb[k2 * 256];
#pragma unroll
            for (int bp = 0; bp < 4; ++bp) {
                ulonglong2 hv = hbase[k2 * 4 + bp];
                ffma2(aB[2 * bp], wb, hv.x);
                ffma2(aB[2 * bp + 1], wb, hv.y);
            }
        }
        float* exf = (float*)exch;
        if (kh) {
#pragma unroll
            for (int b = 0; b < 8; ++b) exf[b * 256 + j] = hsum2(aB[b]);
        }
        __syncthreads();
        if (!kh) {
            float bb = b_base[j];
#pragma unroll
            for (int b = 0; b < 8; ++b)
                exf[b * 256 + j] = fmaxf(hsum2(aB[b]) + exf[b * 256 + j] + bb, 0.f);
        }
        __syncthreads();
    }

    // factorized heads: 64 outputs per CTA
    if (tid < 64) {
        const float* hb = (const float*)exch;
        int b = tid >> 3, a = tid & 7;
        float aD = b_dir[a], aM = b_mag[a];
        const float* __restrict__ wd = w_dir + a * 256;
        const float* __restrict__ wm = w_mag + a * 256;
#pragma unroll 4
        for (int k = 0; k < 256; ++k) {
            float hv = hb[b * 256 + k];
            aD = fmaf(wd[k], hv, aD);
            aM = fmaf(wm[k], hv, aM);
        }
        out[(size_t)(bbase + b) * 8 + a] = tanhf_(aD) * sigmoidf_(aM);
    }
}

// ---------------- launch ----------------------------------------------------------------
extern "C" void kernel_launch(void* const* d_in, const int* in_sizes, int n_in,
                              void* d_out, int out_size) {
    const float* x      = (const float*)d_in[0];
    const float* w_ih   = (const float*)d_in[1];
    const float* w_hh   = (const float*)d_in[2];
    const float* b_ih   = (const float*)d_in[3];
    const float* b_hh   = (const float*)d_in[4];
    const float* w_base = (const float*)d_in[5];
    const float* b_base = (const float*)d_in[6];
    const float* w_dir  = (const float*)d_in[7];
    const float* b_dir  = (const float*)d_in[8];
    const float* w_mag  = (const float*)d_in[9];
    const float* b_mag  = (const float*)d_in[10];

    // 32768*3 + 8192*2 = 114688 elements -> 448 blocks of 256
    prep_kernel<<<448, 256>>>(w_ih, w_hh, w_base);
    actor_kernel<<<128, 512>>>(x, b_ih, b_hh, b_base, w_dir, b_dir, w_mag, b_mag,
                               (float*)d_out);
}

// round 12
// speedup vs baseline: 1.1061x; 1.1061x over previous
#include <cuda_runtime.h>
#include <cstdint>

#define NT 512
#define NS 64

typedef unsigned long long u64;

// ---------------- packed weights, k2-interleaved by gate (same as R9, verified) ---------
__device__ float4 g_whRZ[128 * 256];
__device__ float2 g_whN[128 * 256];
__device__ float4 g_wiRZ[32 * 256];
__device__ float2 g_wiN[32 * 256];
__device__ float2 g_wbP[128 * 256];

// ---------------- f32x2 helpers ---------------------------------------------------------
__device__ __forceinline__ u64 pk2(float a, float b) {
    u64 r;
    asm("mov.b64 %0,{%1,%2};" : "=l"(r)
        : "r"(__float_as_uint(a)), "r"(__float_as_uint(b)));
    return r;
}
__device__ __forceinline__ float2 upk2(u64 v) {
    unsigned lo, hi;
    asm("mov.b64 {%0,%1},%2;" : "=r"(lo), "=r"(hi) : "l"(v));
    return make_float2(__uint_as_float(lo), __uint_as_float(hi));
}
__device__ __forceinline__ void ffma2(u64& d, u64 a, u64 b) {
    asm("fma.rn.f32x2 %0,%1,%2,%3;" : "=l"(d) : "l"(a), "l"(b), "l"(d));
}
__device__ __forceinline__ float hsum2(u64 v) {
    float2 f = upk2(v);
    return f.x + f.y;
}
__device__ __forceinline__ float sigmoidf_(float x) { return 1.f / (1.f + __expf(-x)); }
__device__ __forceinline__ float tanhf_(float x) { return 1.f - 2.f / (__expf(2.f * x) + 1.f); }

// ---------------- cp.async helpers ------------------------------------------------------
__device__ __forceinline__ void cp16(uint32_t dst, const void* src) {
    asm volatile("cp.async.cg.shared.global [%0], [%1], 16;" :: "r"(dst), "l"(src) : "memory");
}
__device__ __forceinline__ void cp8(uint32_t dst, const void* src) {
    asm volatile("cp.async.ca.shared.global [%0], [%1], 8;" :: "r"(dst), "l"(src) : "memory");
}
__device__ __forceinline__ void cp_commit() {
    asm volatile("cp.async.commit_group;" ::: "memory");
}
__device__ __forceinline__ void cp_wait2() {
    asm volatile("cp.async.wait_group 2;" ::: "memory");
}

// ---------------- SMEM layout (dynamic), bytes ------------------------------------------
// [0      , 98304 )  wrz ring: 3 bufs x [4 it][2 kh][256 j] x 16B   (32768/buf)
// [98304  , 147456)  wn  ring: 3 bufs x [4 it][2 kh][256 j] x 8B    (16384/buf)
// [147456 , 155648)  hs : [128 k2][4 bp] ulonglong2
// [155648 , 159744)  xs : [2 buf][32 k2][4 bp] ulonglong2
// [159744 , 192512)  exch: [8 b][256 j] float4
#define OFF_WRZ 0
#define OFF_WN 98304
#define OFF_HS 147456
#define OFF_XS 155648
#define OFF_EXCH 159744
#define SMEM_TOTAL 192512

// ---------------- prep: transpose + pack (identical to R9, verified) --------------------
__global__ void __launch_bounds__(256) prep_kernel(const float* __restrict__ w_ih,
                                                   const float* __restrict__ w_hh,
                                                   const float* __restrict__ w_base) {
    int idx = blockIdx.x * 256 + threadIdx.x;
    if (idx < 32768) {
        int k2 = idx >> 8, j = idx & 255;
        const float* wr = w_hh + (size_t)j * 256;
        const float* wz = w_hh + (size_t)(256 + j) * 256;
        g_whRZ[idx] = make_float4(wr[2 * k2], wr[2 * k2 + 1], wz[2 * k2], wz[2 * k2 + 1]);
        return;
    }
    idx -= 32768;
    if (idx < 32768) {
        int k2 = idx >> 8, j = idx & 255;
        const float* wn = w_hh + (size_t)(512 + j) * 256;
        g_whN[idx] = make_float2(wn[2 * k2], wn[2 * k2 + 1]);
        return;
    }
    idx -= 32768;
    if (idx < 8192) {
        int k2 = idx >> 8, j = idx & 255;
        const float* wr = w_ih + (size_t)j * 64;
        const float* wz = w_ih + (size_t)(256 + j) * 64;
        g_wiRZ[idx] = make_float4(wr[2 * k2], wr[2 * k2 + 1], wz[2 * k2], wz[2 * k2 + 1]);
        return;
    }
    idx -= 8192;
    if (idx < 8192) {
        int k2 = idx >> 8, j = idx & 255;
        const float* wn = w_ih + (size_t)(512 + j) * 64;
        g_wiN[idx] = make_float2(wn[2 * k2], wn[2 * k2 + 1]);
        return;
    }
    idx -= 8192;
    if (idx < 32768) {
        int k2 = idx >> 8, j = idx & 255;
        const float* row = w_base + (size_t)j * 256;
        g_wbP[idx] = make_float2(row[2 * k2], row[2 * k2 + 1]);
    }
}

// prefetch one tile (4 k2-iters) of this thread's own weights into ring buffer pbuf
__device__ __forceinline__ void prefetch_tile(int pt, int pbuf, uint32_t swrz, uint32_t swn,
                                              const char* gRZi, const char* gNi,
                                              const char* gRZh, const char* gNh) {
    uint32_t drz = swrz + pbuf * 32768;
    uint32_t dwn = swn + pbuf * 16384;
    const char* s1;
    const char* s2;
    if (pt < 4) {
        s1 = gRZi + (size_t)pt * 4 * 4096;
        s2 = gNi + (size_t)pt * 4 * 2048;
    } else {
        s1 = gRZh + (size_t)(pt - 4) * 4 * 4096;
        s2 = gNh + (size_t)(pt - 4) * 4 * 2048;
    }
#pragma unroll
    for (int it = 0; it < 4; ++it) {
        cp16(drz + it * 8192, s1 + (size_t)it * 4096);
        cp8(dwn + it * 4096, s2 + (size_t)it * 2048);
    }
    cp_commit();
}

// ---------------- main: 128 CTAs x 512 threads; 8 rows/CTA; thread = (j, k-half) --------
__global__ void __launch_bounds__(512, 1) actor_kernel(
    const float* __restrict__ x, const float* __restrict__ b_ih,
    const float* __restrict__ b_hh, const float* __restrict__ b_base,
    const float* __restrict__ w_dir, const float* __restrict__ b_dir,
    const float* __restrict__ w_mag, const float* __restrict__ b_mag,
    float* __restrict__ out) {
    extern __shared__ char smem[];
    ulonglong2* hs = (ulonglong2*)(smem + OFF_HS);          // [128][4]
    ulonglong2* xs = (ulonglong2*)(smem + OFF_XS);          // [2][32][4]
    float4* exch = (float4*)(smem + OFF_EXCH);              // [8][256]

    const int tid = threadIdx.x;
    const int j = tid & 255;
    const int kh = tid >> 8;
    const int bbase = blockIdx.x * 8;

    hs[tid] = make_ulonglong2(0ULL, 0ULL);

    const float br = b_ih[j] + b_hh[j];
    const float bz = b_ih[256 + j] + b_hh[256 + j];
    const float bi = b_ih[512 + j];
    const float bh = b_hh[512 + j];

    float hreg[8];
#pragma unroll
    for (int i = 0; i < 8; i++) hreg[i] = 0.f;

    // x prefetch: threads 0..127 own (row, 4-float chunk)
    const int xrow = tid >> 4, xc = tid & 15;
    const float* xptr = x + (size_t)(bbase + xrow) * NT * NS + xc * 4;
    float4 xr = make_float4(0.f, 0.f, 0.f, 0.f);
    if (tid < 128) xr = *(const float4*)xptr;

    // per-thread SMEM slots (self-owned) and global weight bases
    uint32_t sb = (uint32_t)__cvta_generic_to_shared(smem);
    const uint32_t swrz = sb + OFF_WRZ + (uint32_t)(kh * 256 + j) * 16;
    const uint32_t swn = sb + OFF_WN + (uint32_t)(kh * 256 + j) * 8;
    const char* thrz = smem + OFF_WRZ + (size_t)(kh * 256 + j) * 16;
    const char* thwn = smem + OFF_WN + (size_t)(kh * 256 + j) * 8;
    const char* gRZi = (const char*)g_wiRZ + (size_t)(kh * 16 * 256 + j) * 16;
    const char* gNi = (const char*)g_wiN + (size_t)(kh * 16 * 256 + j) * 8;
    const char* gRZh = (const char*)g_whRZ + (size_t)(kh * 64 * 256 + j) * 16;
    const char* gNh = (const char*)g_whN + (size_t)(kh * 64 * 256 + j) * 8;

    const ulonglong2* hbase = hs + (size_t)kh * 64 * 4;

    // prologue: tiles 0,1 in flight
    prefetch_tile(0, 0, swrz, swn, gRZi, gNi, gRZh, gNh);
    prefetch_tile(1, 1, swrz, swn, gRZi, gNi, gRZh, gNh);
    int cbuf = 0;

    for (int t = 0; t < NT; ++t) {
        const int buf = t & 1;
        if (tid < 128) {
            u64* xw = (u64*)(xs + (size_t)buf * 128);
            xw[(2 * xc) * 8 + (xrow >> 1) * 2 + (xrow & 1)] = pk2(xr.x, xr.y);
            xw[(2 * xc + 1) * 8 + (xrow >> 1) * 2 + (xrow & 1)] = pk2(xr.z, xr.w);
            if (t + 1 < NT) xr = *(const float4*)(xptr + (size_t)(t + 1) * NS);
        }
        __syncthreads();  // x_t staged; h(t-1) visible; exch free

        u64 aR[8], aZ[8], aNi[8], aNh[8];
#pragma unroll
        for (int b = 0; b < 8; b++) { aR[b] = aZ[b] = aNi[b] = aNh[b] = 0ULL; }

        const ulonglong2* xbase = xs + (size_t)buf * 128 + (size_t)kh * 16 * 4;

        // ---- input tiles 0..3 ----
#pragma unroll 1
        for (int tl = 0; tl < 4; ++tl) {
            int pbuf = cbuf + 2;
            if (pbuf >= 3) pbuf -= 3;
            prefetch_tile(tl + 2, pbuf, swrz, swn, gRZi, gNi, gRZh, gNh);
            cp_wait2();
            const char* c1 = thrz + (size_t)cbuf * 32768;
            const char* c2 = thwn + (size_t)cbuf * 16384;
#pragma unroll
            for (int it = 0; it < 4; ++it) {
                ulonglong2 wrz = *(const ulonglong2*)(c1 + it * 8192);
                u64 wn = *(const u64*)(c2 + it * 4096);
                const ulonglong2* hv4 = xbase + (size_t)(tl * 4 + it) * 4;
#pragma unroll
                for (int bp = 0; bp < 4; ++bp) {
                    ulonglong2 hv = hv4[bp];
                    ffma2(aR[2 * bp], wrz.x, hv.x);
                    ffma2(aR[2 * bp + 1], wrz.x, hv.y);
                    ffma2(aZ[2 * bp], wrz.y, hv.x);
                    ffma2(aZ[2 * bp + 1], wrz.y, hv.y);
                    ffma2(aNi[2 * bp], wn, hv.x);
                    ffma2(aNi[2 * bp + 1], wn, hv.y);
                }
            }
            cbuf = (cbuf == 2) ? 0 : cbuf + 1;
        }
        // ---- recurrent tiles 4..19 ----
#pragma unroll 1
        for (int tl = 4; tl < 20; ++tl) {
            int pt = tl + 2;
            if (pt >= 20) pt -= 20;  // wraps into next step's input tiles (same addresses)
            int pbuf = cbuf + 2;
            if (pbuf >= 3) pbuf -= 3;
            prefetch_tile(pt, pbuf, swrz, swn, gRZi, gNi, gRZh, gNh);
            cp_wait2();
            const char* c1 = thrz + (size_t)cbuf * 32768;
            const char* c2 = thwn + (size_t)cbuf * 16384;
#pragma unroll
            for (int it = 0; it < 4; ++it) {
                ulonglong2 wrz = *(const ulonglong2*)(c1 + it * 8192);
                u64 wn = *(const u64*)(c2 + it * 4096);
                const ulonglong2* hv4 = hbase + (size_t)((tl - 4) * 4 + it) * 4;
#pragma unroll
                for (int bp = 0; bp < 4; ++bp) {
                    ulonglong2 hv = hv4[bp];
                    ffma2(aR[2 * bp], wrz.x, hv.x);
                    ffma2(aR[2 * bp + 1], wrz.x, hv.y);
                    ffma2(aZ[2 * bp], wrz.y, hv.x);
                    ffma2(aZ[2 * bp + 1], wrz.y, hv.y);
                    ffma2(aNh[2 * bp], wn, hv.x);
                    ffma2(aNh[2 * bp + 1], wn, hv.y);
                }
            }
            cbuf = (cbuf == 2) ? 0 : cbuf + 1;
        }

        // kh=1 publishes horizontally-reduced partials
        if (kh) {
#pragma unroll
            for (int b = 0; b < 8; ++b)
                exch[b * 256 + j] = make_float4(hsum2(aR[b]), hsum2(aZ[b]),
                                                hsum2(aNi[b]), hsum2(aNh[b]));
        }
        __syncthreads();  // exch ready; all hs reads done

        // kh=0 combines, gate math, writes new h
        if (!kh) {
            const int k2w = j >> 1, par = j & 1;
#pragma unroll
            for (int b = 0; b < 8; ++b) {
                float4 p = exch[b * 256 + j];
                float r = sigmoidf_(hsum2(aR[b]) + p.x + br);
                float z = sigmoidf_(hsum2(aZ[b]) + p.y + bz);
                float n = tanhf_(hsum2(aNi[b]) + p.z + bi +
                                 r * (hsum2(aNh[b]) + p.w + bh));
                hreg[b] = (1.f - z) * n + z * hreg[b];
                ((float*)(hs + (size_t)k2w * 4 + (b >> 1)))[(b & 1) * 2 + par] = hreg[b];
            }
        }
    }
    __syncthreads();  // final h visible

    // base layer (k-split): hb[b][j] = relu(h[b] . w_base[j] + b_base[j])
    {
        u64 aB[8];
#pragma unroll
        for (int b = 0; b < 8; b++) aB[b] = 0ULL;
        const u64* __restrict__ pWb = (const u64*)g_wbP + (size_t)kh * 64 * 256 + j;
#pragma unroll 4
        for (int k2 = 0; k2 < 64; ++k2) {
            u64 wb = pWb[k2 * 256];
#pragma unroll
            for (int bp = 0; bp < 4; ++bp) {
                ulonglong2 hv = hbase[k2 * 4 + bp];
                ffma2(aB[2 * bp], wb, hv.x);
                ffma2(aB[2 * bp + 1], wb, hv.y);
            }
        }
        float* exf = (float*)exch;
        if (kh) {
#pragma unroll
            for (int b = 0; b < 8; ++b) exf[b * 256 + j] = hsum2(aB[b]);
        }
        __syncthreads();
        if (!kh) {
            float bb = b_base[j];
#pragma unroll
            for (int b = 0; b < 8; ++b)
                exf[b * 256 + j] = fmaxf(hsum2(aB[b]) + exf[b * 256 + j] + bb, 0.f);
        }
        __syncthreads();
    }

    // factorized heads: 64 outputs per CTA
    if (tid < 64) {
        const float* hb = (const float*)exch;
        int b = tid >> 3, a = tid & 7;
        float aD = b_dir[a], aM = b_mag[a];
        const float* __restrict__ wd = w_dir + a * 256;
        const float* __restrict__ wm = w_mag + a * 256;
#pragma unroll 4
        for (int k = 0; k < 256; ++k) {
            float hv = hb[b * 256 + k];
            aD = fmaf(wd[k], hv, aD);
            aM = fmaf(wm[k], hv, aM);
        }
        out[(size_t)(bbase + b) * 8 + a] = tanhf_(aD) * sigmoidf_(aM);
    }
}

// ---------------- launch ----------------------------------------------------------------
extern "C" void kernel_launch(void* const* d_in, const int* in_sizes, int n_in,
                              void* d_out, int out_size) {
    const float* x      = (const float*)d_in[0];
    const float* w_ih   = (const float*)d_in[1];
    const float* w_hh   = (const float*)d_in[2];
    const float* b_ih   = (const float*)d_in[3];
    const float* b_hh   = (const float*)d_in[4];
    const float* w_base = (const float*)d_in[5];
    const float* b_base = (const float*)d_in[6];
    const float* w_dir  = (const float*)d_in[7];
    const float* b_dir  = (const float*)d_in[8];
    const float* w_mag  = (const float*)d_in[9];
    const float* b_mag  = (const float*)d_in[10];

    static int configured = 0;
    if (!configured) {
        cudaFuncSetAttribute(actor_kernel, cudaFuncAttributeMaxDynamicSharedMemorySize,
                             SMEM_TOTAL);
        configured = 1;
    }

    prep_kernel<<<448, 256>>>(w_ih, w_hh, w_base);
    actor_kernel<<<128, 512, SMEM_TOTAL>>>(x, b_ih, b_hh, b_base, w_dir, b_dir, w_mag,
                                           b_mag, (float*)d_out);
}